// round 9
// baseline (speedup 1.0000x reference)
#include <cuda_runtime.h>
#include <cuda_fp16.h>
#include <cstdint>
#include <cstddef>

// Problem shape
#define B_DIM 4096
#define IN_DIM 1024
#define H_DIM 1024
#define K_DIM 2048          // IN + H concatenated along K
// Tiling
#define BM 128              // batch rows per CTA
#define BH 32               // h columns per CTA
#define BN 128              // 4 gates * BH
#define BK 64               // K per stage (64 fp16 = 128B row)
#define STAGES 3
#define NITER (K_DIM / BK)  // 32
#define THREADS 256         // 8 warps, 2x4, warp tile 64x32

// fp16 scratch in PRE-SWIZZLED tiled layout (static device arrays; no allocation)
//   g_xh: [mtile 0..31][stage 0..31] 16KB blocks; 128 rows x 128B, XOR swizzle
//   g_w : [htile 0..31][stage 0..31] 16KB blocks; 128 rows (4 gates x 32) x 128B, XOR swizzle
__device__ __half g_xh[(size_t)B_DIM * K_DIM];
__device__ __half g_w[(size_t)4 * H_DIM * K_DIM];

// Shared memory layout
#define A_BYTES (BM * 128)                         // 16384
#define B_BYTES (BN * 128)                         // 16384
#define STAGE_BYTES (A_BYTES + B_BYTES)            // 32768
#define SMEM_FULL(s)  (16 + 8 * (s))               // full barriers
#define SMEM_EMPTY(s) (48 + 8 * (s))               // empty barriers
#define SMEM_BIAS 128                              // 4*32 floats = 512B
#define SMEM_DATA 2048
#define SMEM_TOTAL (SMEM_DATA + STAGES * STAGE_BYTES)  // 100352  (x2 CTAs = 200704 <= 227KB)
// Epilogue gates buffer overlays stage area: 128 x 136 x 4 = 69632 <= 98304
#define GPITCH 136

__device__ __forceinline__ uint32_t smem_u32(const void* p) {
    uint32_t a;
    asm("{ .reg .u64 t; cvta.to.shared.u64 t, %1; cvt.u32.u64 %0, t; }" : "=r"(a) : "l"(p));
    return a;
}

__device__ __forceinline__ void mbar_init(uint32_t addr, uint32_t cnt) {
    asm volatile("mbarrier.init.shared.b64 [%0], %1;" :: "r"(addr), "r"(cnt) : "memory");
}
__device__ __forceinline__ void mbar_expect_tx(uint32_t addr, uint32_t tx) {
    asm volatile("mbarrier.arrive.expect_tx.shared.b64 _, [%0], %1;" :: "r"(addr), "r"(tx) : "memory");
}
__device__ __forceinline__ void mbar_arrive(uint32_t addr) {
    asm volatile("mbarrier.arrive.shared.b64 _, [%0];" :: "r"(addr) : "memory");
}
__device__ __forceinline__ void mbar_wait(uint32_t addr, uint32_t parity) {
    uint32_t done;
    asm volatile(
        "{\n\t.reg .pred p;\n\t"
        "mbarrier.try_wait.parity.acquire.cta.shared::cta.b64 p, [%1], %2;\n\t"
        "selp.b32 %0, 1, 0, p;\n\t}"
        : "=r"(done) : "r"(addr), "r"(parity) : "memory");
    while (!done) {
        asm volatile(
            "{\n\t.reg .pred p;\n\t"
            "mbarrier.try_wait.parity.acquire.cta.shared::cta.b64 p, [%1], %2, 0x989680;\n\t"
            "selp.b32 %0, 1, 0, p;\n\t}"
            : "=r"(done) : "r"(addr), "r"(parity) : "memory");
    }
}
__device__ __forceinline__ void bulk_g2s(uint32_t dst, const void* src, uint32_t bytes, uint32_t mbar) {
    asm volatile(
        "cp.async.bulk.shared::cluster.global.mbarrier::complete_tx::bytes [%0], [%1], %2, [%3];"
        :: "r"(dst), "l"(src), "r"(bytes), "r"(mbar) : "memory");
}

__device__ __forceinline__ void ldsm4(uint32_t* r, uint32_t addr) {
    asm volatile("ldmatrix.sync.aligned.m8n8.x4.shared.b16 {%0,%1,%2,%3}, [%4];"
                 : "=r"(r[0]), "=r"(r[1]), "=r"(r[2]), "=r"(r[3]) : "r"(addr));
}

__device__ __forceinline__ void mma_f16(float* d, const uint32_t* a, const uint32_t* b) {
    asm volatile(
        "mma.sync.aligned.m16n8k16.row.col.f32.f16.f16.f32 "
        "{%0, %1, %2, %3}, {%4, %5, %6, %7}, {%8, %9}, {%0, %1, %2, %3};"
        : "+f"(d[0]), "+f"(d[1]), "+f"(d[2]), "+f"(d[3])
        : "r"(a[0]), "r"(a[1]), "r"(a[2]), "r"(a[3]), "r"(b[0]), "r"(b[1]));
}

__device__ __forceinline__ float sigmoidf_fast(float x) {
    return 1.0f / (1.0f + __expf(-x));
}
__device__ __forceinline__ float tanhf_fast(float x) {
    float e = __expf(2.0f * x);
    return (e - 1.0f) / (e + 1.0f);
}

// ---------------- merged conversion kernel (writes pre-swizzled tiled layout) ----------------
__global__ void __launch_bounds__(256)
conv_kernel(const float* __restrict__ x, const float* __restrict__ h,
            const float* __restrict__ Wxi, const float* __restrict__ Whi,
            const float* __restrict__ Wxf, const float* __restrict__ Whf,
            const float* __restrict__ Wxg, const float* __restrict__ Whg,
            const float* __restrict__ Wxo, const float* __restrict__ Who) {
    const int half = gridDim.x >> 1;
    size_t i = (size_t)(blockIdx.x % half) * blockDim.x + threadIdx.x;  // 0 .. 1M-1
    int rg     = (int)(i >> 8);          // source row (0..4095)
    int kchunk = (int)(i & 255);         // 16B chunk along K
    int stage  = kchunk >> 3;            // 0..31
    int c      = kchunk & 7;             // chunk within 128B row
    int col    = stage * 64 + c * 8;     // K element index (8 halves)
    const float* src;
    char* dst;
    if (blockIdx.x < half) {
        src = (col < IN_DIM) ? (x + (size_t)rg * IN_DIM + col)
                             : (h + (size_t)rg * H_DIM + (col - IN_DIM));
        int r  = rg & 127;
        int mt = rg >> 7;
        dst = (char*)g_xh + ((size_t)(mt * 32 + stage)) * A_BYTES
            + r * 128 + ((c ^ (r & 7)) << 4);
    } else {
        const float* const Wx[4] = {Wxi, Wxf, Wxg, Wxo};
        const float* const Wh[4] = {Whi, Whf, Whg, Who};
        int gate = rg >> 10;
        int hh   = rg & 1023;
        int ht   = hh >> 5;              // 0..31 h tiles of 32
        int r    = gate * 32 + (hh & 31);// row within 128-row B tile (gate-major)
        src = (col < IN_DIM) ? (Wx[gate] + (size_t)hh * IN_DIM + col)
                             : (Wh[gate] + (size_t)hh * H_DIM + (col - IN_DIM));
        dst = (char*)g_w + ((size_t)(ht * 32 + stage)) * B_BYTES
            + r * 128 + ((c ^ (r & 7)) << 4);
    }
    float4 v0 = *(const float4*)(src);
    float4 v1 = *(const float4*)(src + 4);
    __half2 h0 = __floats2half2_rn(v0.x, v0.y);
    __half2 h1 = __floats2half2_rn(v0.z, v0.w);
    __half2 h2 = __floats2half2_rn(v1.x, v1.y);
    __half2 h3 = __floats2half2_rn(v1.z, v1.w);
    uint4 o;
    o.x = *(uint32_t*)&h0; o.y = *(uint32_t*)&h1;
    o.z = *(uint32_t*)&h2; o.w = *(uint32_t*)&h3;
    *(uint4*)dst = o;
}

// ---------------- main fused GEMM + LSTM kernel ----------------

__global__ void __launch_bounds__(THREADS, 2)
lstm_kernel(const float* __restrict__ cprev,
            const float* __restrict__ bi, const float* __restrict__ bfv,
            const float* __restrict__ bg, const float* __restrict__ bo,
            float* __restrict__ out_h, float* out_h2, float* out_c)
{
    extern __shared__ char smem[];
    const uint32_t sb = smem_u32(smem);
    const int tid  = threadIdx.x;
    const int lane = tid & 31;
    const int warp = tid >> 5;
    const int wm   = warp >> 2;   // 0..1  (64-row tiles)
    const int wn   = warp & 3;    // 0..3  (32-col tiles = gate id)

    const int bid   = blockIdx.x;
    const int htile = bid & 31;   // 32 h tiles
    const int mtile = bid >> 5;   // 32 m tiles
    const int m0 = mtile * BM;
    const int h0 = htile * BH;

    // --- barrier init + bias staging ---
    if (tid == 0) {
        #pragma unroll
        for (int s = 0; s < STAGES; s++) {
            mbar_init(sb + SMEM_FULL(s), 1);     // producer expect_tx
            mbar_init(sb + SMEM_EMPTY(s), 8);    // one arrive per warp
        }
    }
    if (tid < 32) {
        float* bs = (float*)(smem + SMEM_BIAS);
        bs[0 * 32 + tid] = bi[h0 + tid];
        bs[1 * 32 + tid] = bfv[h0 + tid];
        bs[2 * 32 + tid] = bg[h0 + tid];
        bs[3 * 32 + tid] = bo[h0 + tid];
    }
    __syncthreads();

    // --- producer: 2 bulk copies per stage, issued by tid 0 ---
    const char* asrc = (const char*)g_xh + (size_t)mtile * 32 * A_BYTES;
    const char* bsrc = (const char*)g_w  + (size_t)htile * 32 * B_BYTES;
    auto produce = [&](int f) {
        int slot = f % STAGES;
        if (f >= STAGES) mbar_wait(sb + SMEM_EMPTY(slot), (uint32_t)((f / STAGES - 1) & 1));
        uint32_t dst = sb + SMEM_DATA + (uint32_t)slot * STAGE_BYTES;
        uint32_t mb  = sb + SMEM_FULL(slot);
        mbar_expect_tx(mb, STAGE_BYTES);
        bulk_g2s(dst, asrc + (size_t)f * A_BYTES, A_BYTES, mb);
        bulk_g2s(dst + A_BYTES, bsrc + (size_t)f * B_BYTES, B_BYTES, mb);
    };
    if (tid == 0) { produce(0); produce(1); produce(2); }

    // --- ldmatrix per-lane geometry ---
    const int q   = lane >> 3;      // 0..3
    const int qlo = q & 1;
    const int qhi = q >> 1;
    const int lr  = lane & 7;

    uint32_t aoff[4];
    #pragma unroll
    for (int mi = 0; mi < 4; mi++)
        aoff[mi] = (uint32_t)((wm * 64 + mi * 16 + qlo * 8 + lr) * 128);
    uint32_t boff[2];
    #pragma unroll
    for (int p = 0; p < 2; p++)
        boff[p] = (uint32_t)(A_BYTES + (wn * 32 + p * 16 + qhi * 8 + lr) * 128);
    const uint32_t lxor = (uint32_t)lr;

    // --- accumulators: 4 (m) x 4 (n) tiles of 16x8 ---
    float acc[4][4][4];
    #pragma unroll
    for (int mi = 0; mi < 4; mi++)
        #pragma unroll
        for (int ni = 0; ni < 4; ni++)
            #pragma unroll
            for (int r = 0; r < 4; r++) acc[mi][ni][r] = 0.0f;

    // --- main loop: single-buffered fragments, mbarrier-ordered stages ---
    for (int tt = 0; tt < NITER; tt++) {
        const int slot = tt % STAGES;
        const uint32_t scur = sb + SMEM_DATA + (uint32_t)slot * STAGE_BYTES;
        mbar_wait(sb + SMEM_FULL(slot), (uint32_t)((tt / STAGES) & 1));

        #pragma unroll
        for (int kt = 0; kt < 4; kt++) {
            uint32_t af[4][4], bf[4][2];
            const uint32_t ca = (uint32_t)(2 * kt) + (uint32_t)qhi;
            #pragma unroll
            for (int mi = 0; mi < 4; mi++)
                ldsm4(af[mi], scur + aoff[mi] + ((ca ^ lxor) << 4));
            const uint32_t cb = (uint32_t)(2 * kt) + (uint32_t)qlo;
            #pragma unroll
            for (int p = 0; p < 2; p++) {
                uint32_t r[4];
                ldsm4(r, scur + boff[p] + ((cb ^ lxor) << 4));
                bf[2 * p][0]     = r[0];
                bf[2 * p][1]     = r[1];
                bf[2 * p + 1][0] = r[2];
                bf[2 * p + 1][1] = r[3];
            }
            #pragma unroll
            for (int ni = 0; ni < 4; ni++)
                #pragma unroll
                for (int mi = 0; mi < 4; mi++)
                    mma_f16(acc[mi][ni], af[mi], bf[ni]);
        }

        if (lane == 0) mbar_arrive(sb + SMEM_EMPTY(slot));   // done reading slot
        if (tid == 0 && tt + STAGES < NITER) produce(tt + STAGES);
    }
    __syncthreads();

    // --- epilogue: accums -> smem gates buffer [128][GPITCH] ---
    const int g  = lane >> 2;
    const int t4 = lane & 3;
    float* gs = (float*)(smem + SMEM_DATA);
    #pragma unroll
    for (int mi = 0; mi < 4; mi++) {
        #pragma unroll
        for (int ni = 0; ni < 4; ni++) {
            int row = wm * 64 + mi * 16 + g;
            int col = wn * 32 + ni * 8 + 2 * t4;
            *(float2*)(gs + row * GPITCH + col)       = make_float2(acc[mi][ni][0], acc[mi][ni][1]);
            *(float2*)(gs + (row + 8) * GPITCH + col) = make_float2(acc[mi][ni][2], acc[mi][ni][3]);
        }
    }
    __syncthreads();

    // --- pointwise LSTM + writes (float4 over 32 h cols) ---
    const float* bs = (const float*)(smem + SMEM_BIAS);
    #pragma unroll
    for (int rep = 0; rep < 4; rep++) {
        int idx = tid + THREADS * rep;    // 0..1023
        int m  = idx >> 3;                // 0..127
        int h4 = idx & 7;                 // float4 over 32 h cols
        const float* grow = gs + m * GPITCH;

        float4 zi = *(const float4*)(grow + 0 * 32 + h4 * 4);
        float4 zf = *(const float4*)(grow + 1 * 32 + h4 * 4);
        float4 zg = *(const float4*)(grow + 2 * 32 + h4 * 4);
        float4 zo = *(const float4*)(grow + 3 * 32 + h4 * 4);
        float4 vbi = *(const float4*)(bs + 0 * 32 + h4 * 4);
        float4 vbf = *(const float4*)(bs + 1 * 32 + h4 * 4);
        float4 vbg = *(const float4*)(bs + 2 * 32 + h4 * 4);
        float4 vbo = *(const float4*)(bs + 3 * 32 + h4 * 4);

        size_t go = (size_t)(m0 + m) * H_DIM + h0 + h4 * 4;
        float4 cp = *(const float4*)(cprev + go);

        float hv[4], cv[4];
        float azi[4] = {zi.x, zi.y, zi.z, zi.w};
        float azf[4] = {zf.x, zf.y, zf.z, zf.w};
        float azg[4] = {zg.x, zg.y, zg.z, zg.w};
        float azo[4] = {zo.x, zo.y, zo.z, zo.w};
        float abi[4] = {vbi.x, vbi.y, vbi.z, vbi.w};
        float abf[4] = {vbf.x, vbf.y, vbf.z, vbf.w};
        float abg[4] = {vbg.x, vbg.y, vbg.z, vbg.w};
        float abo[4] = {vbo.x, vbo.y, vbo.z, vbo.w};
        float acp[4] = {cp.x, cp.y, cp.z, cp.w};

        #pragma unroll
        for (int j = 0; j < 4; j++) {
            float ig = sigmoidf_fast(azi[j] + abi[j]);
            float fg = sigmoidf_fast(azf[j] + abf[j]);
            float gg = tanhf_fast(azg[j] + abg[j]);
            float og = sigmoidf_fast(azo[j] + abo[j]);
            cv[j] = fg * acp[j] + ig * gg;
            hv[j] = og * tanhf_fast(cv[j]);
        }
        float4 hv4 = make_float4(hv[0], hv[1], hv[2], hv[3]);
        float4 cv4 = make_float4(cv[0], cv[1], cv[2], cv[3]);
        *(float4*)(out_h + go) = hv4;
        if (out_h2) *(float4*)(out_h2 + go) = hv4;
        if (out_c)  *(float4*)(out_c + go)  = cv4;
    }
}

extern "C" void kernel_launch(void* const* d_in, const int* in_sizes, int n_in,
                              void* d_out, int out_size) {
    const float* x      = (const float*)d_in[0];
    const float* h_prev = (const float*)d_in[1];
    const float* c_prev = (const float*)d_in[2];
    const float* W_ii = (const float*)d_in[3];
    const float* W_hi = (const float*)d_in[4];
    const float* b_i  = (const float*)d_in[5];
    const float* W_if = (const float*)d_in[6];
    const float* W_hf = (const float*)d_in[7];
    const float* b_f  = (const float*)d_in[8];
    const float* W_ig = (const float*)d_in[9];
    const float* W_hg = (const float*)d_in[10];
    const float* b_g  = (const float*)d_in[11];
    const float* W_io = (const float*)d_in[12];
    const float* W_ho = (const float*)d_in[13];
    const float* b_o  = (const float*)d_in[14];

    float* out = (float*)d_out;
    const int HB = B_DIM * H_DIM;   // 4194304
    float* oh  = out;
    float* oh2 = nullptr;
    float* oc  = nullptr;
    if (out_size >= 3 * HB)      { oh2 = out + HB; oc = out + 2 * HB; }
    else if (out_size >= 2 * HB) { oc = out + HB; }

    static bool attr_set = false;
    if (!attr_set) {
        cudaFuncSetAttribute(lstm_kernel, cudaFuncAttributeMaxDynamicSharedMemorySize, SMEM_TOTAL);
        attr_set = true;
    }

    // fp16 conversion pre-pass (merged; writes pre-swizzled tiled layout)
    {
        int n8 = (B_DIM * K_DIM) / 8;     // 1,048,576 chunks per half
        conv_kernel<<<2 * (n8 / 256), 256>>>(x, h_prev,
                                             W_ii, W_hi, W_if, W_hf,
                                             W_ig, W_hg, W_io, W_ho);
    }

    lstm_kernel<<<(B_DIM / BM) * (H_DIM / BH), THREADS, SMEM_TOTAL>>>(
        c_prev, b_i, b_f, b_g, b_o, oh, oh2, oc);
}

// round 10
// speedup vs baseline: 1.2907x; 1.2907x over previous
#include <cuda_runtime.h>
#include <cuda_fp16.h>
#include <cstdint>
#include <cstddef>

// Problem shape
#define B_DIM 4096
#define IN_DIM 1024
#define H_DIM 1024
#define K_DIM 2048          // IN + H concatenated along K
// Tiling
#define BM 128              // batch rows per CTA
#define BH 32               // h columns per CTA
#define BN 128              // 4 gates * BH
#define BK 64               // K per stage (64 fp16 = 128B row)
#define STAGES 3
#define NITER (K_DIM / BK)  // 32
#define THREADS 128         // 4 warps, 2x2, warp tile 64x64

// fp16 scratch in PRE-SWIZZLED tiled layout (static device arrays; no allocation)
//   g_xh: [mtile 0..31][stage 0..31] 16KB blocks; 128 rows x 128B, XOR swizzle
//   g_w : [htile 0..31][stage 0..31] 16KB blocks; 128 rows (4 gates x 32) x 128B, XOR swizzle
__device__ __half g_xh[(size_t)B_DIM * K_DIM];
__device__ __half g_w[(size_t)4 * H_DIM * K_DIM];

// Shared memory layout
#define A_BYTES (BM * 128)                         // 16384
#define B_BYTES (BN * 128)                         // 16384
#define STAGE_BYTES (A_BYTES + B_BYTES)            // 32768
#define SMEM_FULL(s)  (16 + 8 * (s))               // full barriers
#define SMEM_EMPTY(s) (48 + 8 * (s))               // empty barriers
#define SMEM_BIAS 128                              // 4*32 floats = 512B
#define SMEM_DATA 2048
#define SMEM_TOTAL (SMEM_DATA + STAGES * STAGE_BYTES)  // 100352  (x2 CTAs <= 227KB)
// Epilogue gates buffer overlays stage area: 128 x 136 x 4 = 69632 <= 98304
#define GPITCH 136

__device__ __forceinline__ uint32_t smem_u32(const void* p) {
    uint32_t a;
    asm("{ .reg .u64 t; cvta.to.shared.u64 t, %1; cvt.u32.u64 %0, t; }" : "=r"(a) : "l"(p));
    return a;
}

__device__ __forceinline__ void mbar_init(uint32_t addr, uint32_t cnt) {
    asm volatile("mbarrier.init.shared.b64 [%0], %1;" :: "r"(addr), "r"(cnt) : "memory");
}
__device__ __forceinline__ void mbar_expect_tx(uint32_t addr, uint32_t tx) {
    asm volatile("mbarrier.arrive.expect_tx.shared.b64 _, [%0], %1;" :: "r"(addr), "r"(tx) : "memory");
}
__device__ __forceinline__ void mbar_arrive(uint32_t addr) {
    asm volatile("mbarrier.arrive.shared.b64 _, [%0];" :: "r"(addr) : "memory");
}
__device__ __forceinline__ void mbar_wait(uint32_t addr, uint32_t parity) {
    uint32_t done;
    asm volatile(
        "{\n\t.reg .pred p;\n\t"
        "mbarrier.try_wait.parity.acquire.cta.shared::cta.b64 p, [%1], %2;\n\t"
        "selp.b32 %0, 1, 0, p;\n\t}"
        : "=r"(done) : "r"(addr), "r"(parity) : "memory");
    while (!done) {
        asm volatile(
            "{\n\t.reg .pred p;\n\t"
            "mbarrier.try_wait.parity.acquire.cta.shared::cta.b64 p, [%1], %2, 0x989680;\n\t"
            "selp.b32 %0, 1, 0, p;\n\t}"
            : "=r"(done) : "r"(addr), "r"(parity) : "memory");
    }
}
__device__ __forceinline__ void bulk_g2s(uint32_t dst, const void* src, uint32_t bytes, uint32_t mbar) {
    asm volatile(
        "cp.async.bulk.shared::cluster.global.mbarrier::complete_tx::bytes [%0], [%1], %2, [%3];"
        :: "r"(dst), "l"(src), "r"(bytes), "r"(mbar) : "memory");
}

__device__ __forceinline__ void ldsm4(uint32_t* r, uint32_t addr) {
    asm volatile("ldmatrix.sync.aligned.m8n8.x4.shared.b16 {%0,%1,%2,%3}, [%4];"
                 : "=r"(r[0]), "=r"(r[1]), "=r"(r[2]), "=r"(r[3]) : "r"(addr));
}

__device__ __forceinline__ void mma_f16(float* d, const uint32_t* a, const uint32_t* b) {
    asm volatile(
        "mma.sync.aligned.m16n8k16.row.col.f32.f16.f16.f32 "
        "{%0, %1, %2, %3}, {%4, %5, %6, %7}, {%8, %9}, {%0, %1, %2, %3};"
        : "+f"(d[0]), "+f"(d[1]), "+f"(d[2]), "+f"(d[3])
        : "r"(a[0]), "r"(a[1]), "r"(a[2]), "r"(a[3]), "r"(b[0]), "r"(b[1]));
}

__device__ __forceinline__ float sigmoidf_fast(float x) {
    return 1.0f / (1.0f + __expf(-x));
}
__device__ __forceinline__ float tanhf_fast(float x) {
    float e = __expf(2.0f * x);
    return (e - 1.0f) / (e + 1.0f);
}

// ---------------- merged conversion kernel (writes pre-swizzled tiled layout) ----------------
__global__ void __launch_bounds__(256)
conv_kernel(const float* __restrict__ x, const float* __restrict__ h,
            const float* __restrict__ Wxi, const float* __restrict__ Whi,
            const float* __restrict__ Wxf, const float* __restrict__ Whf,
            const float* __restrict__ Wxg, const float* __restrict__ Whg,
            const float* __restrict__ Wxo, const float* __restrict__ Who) {
    const int half = gridDim.x >> 1;
    size_t i = (size_t)(blockIdx.x % half) * blockDim.x + threadIdx.x;  // 0 .. 1M-1
    int rg     = (int)(i >> 8);          // source row (0..4095)
    int kchunk = (int)(i & 255);         // 16B chunk along K
    int stage  = kchunk >> 3;            // 0..31
    int c      = kchunk & 7;             // chunk within 128B row
    int col    = stage * 64 + c * 8;     // K element index (8 halves)
    const float* src;
    char* dst;
    if (blockIdx.x < half) {
        src = (col < IN_DIM) ? (x + (size_t)rg * IN_DIM + col)
                             : (h + (size_t)rg * H_DIM + (col - IN_DIM));
        int r  = rg & 127;
        int mt = rg >> 7;
        dst = (char*)g_xh + ((size_t)(mt * 32 + stage)) * A_BYTES
            + r * 128 + ((c ^ (r & 7)) << 4);
    } else {
        const float* const Wx[4] = {Wxi, Wxf, Wxg, Wxo};
        const float* const Wh[4] = {Whi, Whf, Whg, Who};
        int gate = rg >> 10;
        int hh   = rg & 1023;
        int ht   = hh >> 5;              // 0..31 h tiles of 32
        int r    = gate * 32 + (hh & 31);// row within 128-row B tile (gate-major)
        src = (col < IN_DIM) ? (Wx[gate] + (size_t)hh * IN_DIM + col)
                             : (Wh[gate] + (size_t)hh * H_DIM + (col - IN_DIM));
        dst = (char*)g_w + ((size_t)(ht * 32 + stage)) * B_BYTES
            + r * 128 + ((c ^ (r & 7)) << 4);
    }
    float4 v0 = *(const float4*)(src);
    float4 v1 = *(const float4*)(src + 4);
    __half2 h0 = __floats2half2_rn(v0.x, v0.y);
    __half2 h1 = __floats2half2_rn(v0.z, v0.w);
    __half2 h2 = __floats2half2_rn(v1.x, v1.y);
    __half2 h3 = __floats2half2_rn(v1.z, v1.w);
    uint4 o;
    o.x = *(uint32_t*)&h0; o.y = *(uint32_t*)&h1;
    o.z = *(uint32_t*)&h2; o.w = *(uint32_t*)&h3;
    *(uint4*)dst = o;
}

// ---------------- main fused GEMM + LSTM kernel ----------------
// 4 warps (one per SMSP), 2 CTAs/SM: big 64x64 warp tiles for low LDSM/MMA,
// cross-CTA overlap for latency cover.

__global__ void __launch_bounds__(THREADS, 2)
lstm_kernel(const float* __restrict__ cprev,
            const float* __restrict__ bi, const float* __restrict__ bfv,
            const float* __restrict__ bg, const float* __restrict__ bo,
            float* __restrict__ out_h, float* out_h2, float* out_c)
{
    extern __shared__ char smem[];
    const uint32_t sb = smem_u32(smem);
    const int tid  = threadIdx.x;
    const int lane = tid & 31;
    const int warp = tid >> 5;
    const int wm   = warp >> 1;   // 0..1  (64-row tiles)
    const int wn   = warp & 1;    // 0..1  (64-col tiles)

    const int bid   = blockIdx.x;
    const int htile = bid & 31;   // 32 h tiles
    const int mtile = bid >> 5;   // 32 m tiles
    const int m0 = mtile * BM;
    const int h0 = htile * BH;

    // --- barrier init + bias staging ---
    if (tid == 0) {
        #pragma unroll
        for (int s = 0; s < STAGES; s++) {
            mbar_init(sb + SMEM_FULL(s), 1);     // producer expect_tx
            mbar_init(sb + SMEM_EMPTY(s), 4);    // one arrive per warp
        }
    }
    if (tid < 32) {
        float* bs = (float*)(smem + SMEM_BIAS);
        bs[0 * 32 + tid] = bi[h0 + tid];
        bs[1 * 32 + tid] = bfv[h0 + tid];
        bs[2 * 32 + tid] = bg[h0 + tid];
        bs[3 * 32 + tid] = bo[h0 + tid];
    }
    __syncthreads();

    // --- producer: 2 bulk copies per stage, issued by tid 0 ---
    const char* asrc = (const char*)g_xh + (size_t)mtile * 32 * A_BYTES;
    const char* bsrc = (const char*)g_w  + (size_t)htile * 32 * B_BYTES;
    auto produce = [&](int f) {
        int slot = f % STAGES;
        if (f >= STAGES) mbar_wait(sb + SMEM_EMPTY(slot), (uint32_t)((f / STAGES - 1) & 1));
        uint32_t dst = sb + SMEM_DATA + (uint32_t)slot * STAGE_BYTES;
        uint32_t mb  = sb + SMEM_FULL(slot);
        mbar_expect_tx(mb, STAGE_BYTES);
        bulk_g2s(dst, asrc + (size_t)f * A_BYTES, A_BYTES, mb);
        bulk_g2s(dst + A_BYTES, bsrc + (size_t)f * B_BYTES, B_BYTES, mb);
    };
    if (tid == 0) { produce(0); produce(1); produce(2); }

    // --- ldmatrix per-lane geometry ---
    const int q   = lane >> 3;      // 0..3
    const int qlo = q & 1;
    const int qhi = q >> 1;
    const int lr  = lane & 7;

    uint32_t aoff[4];
    #pragma unroll
    for (int mi = 0; mi < 4; mi++)
        aoff[mi] = (uint32_t)((wm * 64 + mi * 16 + qlo * 8 + lr) * 128);
    uint32_t boff[4];
    #pragma unroll
    for (int p = 0; p < 4; p++)
        boff[p] = (uint32_t)(A_BYTES + (wn * 64 + p * 16 + qhi * 8 + lr) * 128);
    const uint32_t lxor = (uint32_t)lr;

    // --- accumulators: 4 (m) x 8 (n) tiles of 16x8 ---
    float acc[4][8][4];
    #pragma unroll
    for (int mi = 0; mi < 4; mi++)
        #pragma unroll
        for (int ni = 0; ni < 8; ni++)
            #pragma unroll
            for (int r = 0; r < 4; r++) acc[mi][ni][r] = 0.0f;

    // --- main loop: single-buffered fragments, mbarrier-ordered stages ---
    for (int tt = 0; tt < NITER; tt++) {
        const int slot = tt % STAGES;
        const uint32_t scur = sb + SMEM_DATA + (uint32_t)slot * STAGE_BYTES;
        mbar_wait(sb + SMEM_FULL(slot), (uint32_t)((tt / STAGES) & 1));

        #pragma unroll
        for (int kt = 0; kt < 4; kt++) {
            uint32_t af[4][4], bf[8][2];
            const uint32_t ca = (uint32_t)(2 * kt) + (uint32_t)qhi;
            #pragma unroll
            for (int mi = 0; mi < 4; mi++)
                ldsm4(af[mi], scur + aoff[mi] + ((ca ^ lxor) << 4));
            const uint32_t cb = (uint32_t)(2 * kt) + (uint32_t)qlo;
            #pragma unroll
            for (int p = 0; p < 4; p++) {
                uint32_t r[4];
                ldsm4(r, scur + boff[p] + ((cb ^ lxor) << 4));
                bf[2 * p][0]     = r[0];
                bf[2 * p][1]     = r[1];
                bf[2 * p + 1][0] = r[2];
                bf[2 * p + 1][1] = r[3];
            }
            #pragma unroll
            for (int ni = 0; ni < 8; ni++)
                #pragma unroll
                for (int mi = 0; mi < 4; mi++)
                    mma_f16(acc[mi][ni], af[mi], bf[ni]);
        }

        if (lane == 0) mbar_arrive(sb + SMEM_EMPTY(slot));   // done reading slot
        if (tid == 0 && tt + STAGES < NITER) produce(tt + STAGES);
    }
    __syncthreads();

    // --- epilogue: accums -> smem gates buffer [128][GPITCH] ---
    const int g  = lane >> 2;
    const int t4 = lane & 3;
    float* gs = (float*)(smem + SMEM_DATA);
    #pragma unroll
    for (int mi = 0; mi < 4; mi++) {
        #pragma unroll
        for (int ni = 0; ni < 8; ni++) {
            int row = wm * 64 + mi * 16 + g;
            int col = wn * 64 + ni * 8 + 2 * t4;
            *(float2*)(gs + row * GPITCH + col)       = make_float2(acc[mi][ni][0], acc[mi][ni][1]);
            *(float2*)(gs + (row + 8) * GPITCH + col) = make_float2(acc[mi][ni][2], acc[mi][ni][3]);
        }
    }
    __syncthreads();

    // --- pointwise LSTM + writes (float4 over 32 h cols) ---
    const float* bs = (const float*)(smem + SMEM_BIAS);
    #pragma unroll
    for (int rep = 0; rep < 8; rep++) {
        int idx = tid + THREADS * rep;    // 0..1023
        int m  = idx >> 3;                // 0..127
        int h4 = idx & 7;                 // float4 over 32 h cols
        const float* grow = gs + m * GPITCH;

        float4 zi = *(const float4*)(grow + 0 * 32 + h4 * 4);
        float4 zf = *(const float4*)(grow + 1 * 32 + h4 * 4);
        float4 zg = *(const float4*)(grow + 2 * 32 + h4 * 4);
        float4 zo = *(const float4*)(grow + 3 * 32 + h4 * 4);
        float4 vbi = *(const float4*)(bs + 0 * 32 + h4 * 4);
        float4 vbf = *(const float4*)(bs + 1 * 32 + h4 * 4);
        float4 vbg = *(const float4*)(bs + 2 * 32 + h4 * 4);
        float4 vbo = *(const float4*)(bs + 3 * 32 + h4 * 4);

        size_t go = (size_t)(m0 + m) * H_DIM + h0 + h4 * 4;
        float4 cp = *(const float4*)(cprev + go);

        float hv[4], cv[4];
        float azi[4] = {zi.x, zi.y, zi.z, zi.w};
        float azf[4] = {zf.x, zf.y, zf.z, zf.w};
        float azg[4] = {zg.x, zg.y, zg.z, zg.w};
        float azo[4] = {zo.x, zo.y, zo.z, zo.w};
        float abi[4] = {vbi.x, vbi.y, vbi.z, vbi.w};
        float abf[4] = {vbf.x, vbf.y, vbf.z, vbf.w};
        float abg[4] = {vbg.x, vbg.y, vbg.z, vbg.w};
        float abo[4] = {vbo.x, vbo.y, vbo.z, vbo.w};
        float acp[4] = {cp.x, cp.y, cp.z, cp.w};

        #pragma unroll
        for (int j = 0; j < 4; j++) {
            float ig = sigmoidf_fast(azi[j] + abi[j]);
            float fg = sigmoidf_fast(azf[j] + abf[j]);
            float gg = tanhf_fast(azg[j] + abg[j]);
            float og = sigmoidf_fast(azo[j] + abo[j]);
            cv[j] = fg * acp[j] + ig * gg;
            hv[j] = og * tanhf_fast(cv[j]);
        }
        float4 hv4 = make_float4(hv[0], hv[1], hv[2], hv[3]);
        float4 cv4 = make_float4(cv[0], cv[1], cv[2], cv[3]);
        *(float4*)(out_h + go) = hv4;
        if (out_h2) *(float4*)(out_h2 + go) = hv4;
        if (out_c)  *(float4*)(out_c + go)  = cv4;
    }
}

extern "C" void kernel_launch(void* const* d_in, const int* in_sizes, int n_in,
                              void* d_out, int out_size) {
    const float* x      = (const float*)d_in[0];
    const float* h_prev = (const float*)d_in[1];
    const float* c_prev = (const float*)d_in[2];
    const float* W_ii = (const float*)d_in[3];
    const float* W_hi = (const float*)d_in[4];
    const float* b_i  = (const float*)d_in[5];
    const float* W_if = (const float*)d_in[6];
    const float* W_hf = (const float*)d_in[7];
    const float* b_f  = (const float*)d_in[8];
    const float* W_ig = (const float*)d_in[9];
    const float* W_hg = (const float*)d_in[10];
    const float* b_g  = (const float*)d_in[11];
    const float* W_io = (const float*)d_in[12];
    const float* W_ho = (const float*)d_in[13];
    const float* b_o  = (const float*)d_in[14];

    float* out = (float*)d_out;
    const int HB = B_DIM * H_DIM;   // 4194304
    float* oh  = out;
    float* oh2 = nullptr;
    float* oc  = nullptr;
    if (out_size >= 3 * HB)      { oh2 = out + HB; oc = out + 2 * HB; }
    else if (out_size >= 2 * HB) { oc = out + HB; }

    static bool attr_set = false;
    if (!attr_set) {
        cudaFuncSetAttribute(lstm_kernel, cudaFuncAttributeMaxDynamicSharedMemorySize, SMEM_TOTAL);
        attr_set = true;
    }

    // fp16 conversion pre-pass (merged; writes pre-swizzled tiled layout)
    {
        int n8 = (B_DIM * K_DIM) / 8;     // 1,048,576 chunks per half
        conv_kernel<<<2 * (n8 / 256), 256>>>(x, h_prev,
                                             W_ii, W_hi, W_if, W_hf,
                                             W_ig, W_hg, W_io, W_ho);
    }

    lstm_kernel<<<(B_DIM / BM) * (H_DIM / BH), THREADS, SMEM_TOTAL>>>(
        c_prev, b_i, b_f, b_g, b_o, oh, oh2, oc);
}

// round 11
// speedup vs baseline: 1.3532x; 1.0484x over previous
#include <cuda_runtime.h>
#include <cuda_fp16.h>
#include <cstdint>
#include <cstddef>

// Problem shape
#define B_DIM 4096
#define IN_DIM 1024
#define H_DIM 1024
#define K_DIM 2048          // IN + H concatenated along K
// Tiling
#define BM 128              // batch rows per CTA
#define BH 32               // h columns per CTA
#define BN 128              // 4 gates * BH
#define BK 64               // K per stage (64 fp16 = 128B row)
#define STAGES 3
#define NITER (K_DIM / BK)  // 32
#define THREADS 128         // 4 warps, 2x2, warp tile 64x64

// fp16 scratch in PRE-SWIZZLED tiled layout (static device arrays; no allocation)
//   g_xh: [mtile 0..31][stage 0..31] 16KB blocks; 128 rows x 128B, XOR swizzle
//   g_w : [htile 0..31][stage 0..31] 16KB blocks; 128 rows (4 gates x 32) x 128B, XOR swizzle
__device__ __half g_xh[(size_t)B_DIM * K_DIM];
__device__ __half g_w[(size_t)4 * H_DIM * K_DIM];

// Shared memory layout
#define A_BYTES (BM * 128)                         // 16384
#define B_BYTES (BN * 128)                         // 16384
#define STAGE_BYTES (A_BYTES + B_BYTES)            // 32768
#define SMEM_FULL(s)  (16 + 8 * (s))               // full barriers
#define SMEM_EMPTY(s) (48 + 8 * (s))               // empty barriers
#define SMEM_BIAS 128                              // 4*32 floats = 512B
#define SMEM_DATA 2048
#define SMEM_TOTAL (SMEM_DATA + STAGES * STAGE_BYTES)  // 100352  (x2 CTAs <= 227KB)
// Epilogue gates buffer overlays stage area: 128 x 136 x 4 = 69632 <= 98304
#define GPITCH 136

__device__ __forceinline__ uint32_t smem_u32(const void* p) {
    uint32_t a;
    asm("{ .reg .u64 t; cvta.to.shared.u64 t, %1; cvt.u32.u64 %0, t; }" : "=r"(a) : "l"(p));
    return a;
}

__device__ __forceinline__ void mbar_init(uint32_t addr, uint32_t cnt) {
    asm volatile("mbarrier.init.shared.b64 [%0], %1;" :: "r"(addr), "r"(cnt) : "memory");
}
__device__ __forceinline__ void mbar_expect_tx(uint32_t addr, uint32_t tx) {
    asm volatile("mbarrier.arrive.expect_tx.shared.b64 _, [%0], %1;" :: "r"(addr), "r"(tx) : "memory");
}
__device__ __forceinline__ void mbar_arrive(uint32_t addr) {
    asm volatile("mbarrier.arrive.shared.b64 _, [%0];" :: "r"(addr) : "memory");
}
__device__ __forceinline__ void mbar_wait(uint32_t addr, uint32_t parity) {
    uint32_t done;
    asm volatile(
        "{\n\t.reg .pred p;\n\t"
        "mbarrier.try_wait.parity.acquire.cta.shared::cta.b64 p, [%1], %2;\n\t"
        "selp.b32 %0, 1, 0, p;\n\t}"
        : "=r"(done) : "r"(addr), "r"(parity) : "memory");
    while (!done) {
        asm volatile(
            "{\n\t.reg .pred p;\n\t"
            "mbarrier.try_wait.parity.acquire.cta.shared::cta.b64 p, [%1], %2, 0x989680;\n\t"
            "selp.b32 %0, 1, 0, p;\n\t}"
            : "=r"(done) : "r"(addr), "r"(parity) : "memory");
    }
}
__device__ __forceinline__ void bulk_g2s(uint32_t dst, const void* src, uint32_t bytes, uint32_t mbar) {
    asm volatile(
        "cp.async.bulk.shared::cluster.global.mbarrier::complete_tx::bytes [%0], [%1], %2, [%3];"
        :: "r"(dst), "l"(src), "r"(bytes), "r"(mbar) : "memory");
}

__device__ __forceinline__ void ldsm4(uint32_t* r, uint32_t addr) {
    asm volatile("ldmatrix.sync.aligned.m8n8.x4.shared.b16 {%0,%1,%2,%3}, [%4];"
                 : "=r"(r[0]), "=r"(r[1]), "=r"(r[2]), "=r"(r[3]) : "r"(addr));
}

__device__ __forceinline__ void mma_f16(float* d, const uint32_t* a, const uint32_t* b) {
    asm volatile(
        "mma.sync.aligned.m16n8k16.row.col.f32.f16.f16.f32 "
        "{%0, %1, %2, %3}, {%4, %5, %6, %7}, {%8, %9}, {%0, %1, %2, %3};"
        : "+f"(d[0]), "+f"(d[1]), "+f"(d[2]), "+f"(d[3])
        : "r"(a[0]), "r"(a[1]), "r"(a[2]), "r"(a[3]), "r"(b[0]), "r"(b[1]));
}

__device__ __forceinline__ float sigmoidf_fast(float x) {
    return 1.0f / (1.0f + __expf(-x));
}
__device__ __forceinline__ float tanhf_fast(float x) {
    float e = __expf(2.0f * x);
    return (e - 1.0f) / (e + 1.0f);
}

// ---------------- merged conversion kernel (writes pre-swizzled tiled layout) ----------------
__global__ void __launch_bounds__(256)
conv_kernel(const float* __restrict__ x, const float* __restrict__ h,
            const float* __restrict__ Wxi, const float* __restrict__ Whi,
            const float* __restrict__ Wxf, const float* __restrict__ Whf,
            const float* __restrict__ Wxg, const float* __restrict__ Whg,
            const float* __restrict__ Wxo, const float* __restrict__ Who) {
    const int half = gridDim.x >> 1;
    size_t i = (size_t)(blockIdx.x % half) * blockDim.x + threadIdx.x;  // 0 .. 1M-1
    int rg     = (int)(i >> 8);          // source row (0..4095)
    int kchunk = (int)(i & 255);         // 16B chunk along K
    int stage  = kchunk >> 3;            // 0..31
    int c      = kchunk & 7;             // chunk within 128B row
    int col    = stage * 64 + c * 8;     // K element index (8 halves)
    const float* src;
    char* dst;
    if (blockIdx.x < half) {
        src = (col < IN_DIM) ? (x + (size_t)rg * IN_DIM + col)
                             : (h + (size_t)rg * H_DIM + (col - IN_DIM));
        int r  = rg & 127;
        int mt = rg >> 7;
        dst = (char*)g_xh + ((size_t)(mt * 32 + stage)) * A_BYTES
            + r * 128 + ((c ^ (r & 7)) << 4);
    } else {
        const float* const Wx[4] = {Wxi, Wxf, Wxg, Wxo};
        const float* const Wh[4] = {Whi, Whf, Whg, Who};
        int gate = rg >> 10;
        int hh   = rg & 1023;
        int ht   = hh >> 5;              // 0..31 h tiles of 32
        int r    = gate * 32 + (hh & 31);// row within 128-row B tile (gate-major)
        src = (col < IN_DIM) ? (Wx[gate] + (size_t)hh * IN_DIM + col)
                             : (Wh[gate] + (size_t)hh * H_DIM + (col - IN_DIM));
        dst = (char*)g_w + ((size_t)(ht * 32 + stage)) * B_BYTES
            + r * 128 + ((c ^ (r & 7)) << 4);
    }
    float4 v0 = *(const float4*)(src);
    float4 v1 = *(const float4*)(src + 4);
    __half2 h0 = __floats2half2_rn(v0.x, v0.y);
    __half2 h1 = __floats2half2_rn(v0.z, v0.w);
    __half2 h2 = __floats2half2_rn(v1.x, v1.y);
    __half2 h3 = __floats2half2_rn(v1.z, v1.w);
    uint4 o;
    o.x = *(uint32_t*)&h0; o.y = *(uint32_t*)&h1;
    o.z = *(uint32_t*)&h2; o.w = *(uint32_t*)&h3;
    *(uint4*)dst = o;
}

// ---------------- main fused GEMM + LSTM kernel ----------------
// 4 warps (one per SMSP), 2 CTAs/SM, 64x64 warp tiles, kt-level fragment
// double-buffering to hide ldsm latency inside each warp.

__global__ void __launch_bounds__(THREADS, 2)
lstm_kernel(const float* __restrict__ cprev,
            const float* __restrict__ bi, const float* __restrict__ bfv,
            const float* __restrict__ bg, const float* __restrict__ bo,
            float* __restrict__ out_h, float* out_h2, float* out_c)
{
    extern __shared__ char smem[];
    const uint32_t sb = smem_u32(smem);
    const int tid  = threadIdx.x;
    const int lane = tid & 31;
    const int warp = tid >> 5;
    const int wm   = warp >> 1;   // 0..1  (64-row tiles)
    const int wn   = warp & 1;    // 0..1  (64-col tiles)

    const int bid   = blockIdx.x;
    const int htile = bid & 31;   // 32 h tiles
    const int mtile = bid >> 5;   // 32 m tiles
    const int m0 = mtile * BM;
    const int h0 = htile * BH;

    // --- barrier init + bias staging ---
    if (tid == 0) {
        #pragma unroll
        for (int s = 0; s < STAGES; s++) {
            mbar_init(sb + SMEM_FULL(s), 1);     // producer expect_tx
            mbar_init(sb + SMEM_EMPTY(s), 4);    // one arrive per warp
        }
    }
    if (tid < 32) {
        float* bs = (float*)(smem + SMEM_BIAS);
        bs[0 * 32 + tid] = bi[h0 + tid];
        bs[1 * 32 + tid] = bfv[h0 + tid];
        bs[2 * 32 + tid] = bg[h0 + tid];
        bs[3 * 32 + tid] = bo[h0 + tid];
    }
    __syncthreads();

    // --- producer: 2 bulk copies per stage, issued by tid 0 ---
    const char* asrc = (const char*)g_xh + (size_t)mtile * 32 * A_BYTES;
    const char* bsrc = (const char*)g_w  + (size_t)htile * 32 * B_BYTES;
    auto produce = [&](int f) {
        int slot = f % STAGES;
        if (f >= STAGES) mbar_wait(sb + SMEM_EMPTY(slot), (uint32_t)((f / STAGES - 1) & 1));
        uint32_t dst = sb + SMEM_DATA + (uint32_t)slot * STAGE_BYTES;
        uint32_t mb  = sb + SMEM_FULL(slot);
        mbar_expect_tx(mb, STAGE_BYTES);
        bulk_g2s(dst, asrc + (size_t)f * A_BYTES, A_BYTES, mb);
        bulk_g2s(dst + A_BYTES, bsrc + (size_t)f * B_BYTES, B_BYTES, mb);
    };
    if (tid == 0) { produce(0); produce(1); produce(2); }

    // --- ldmatrix per-lane geometry ---
    const int q   = lane >> 3;      // 0..3
    const int qlo = q & 1;
    const int qhi = q >> 1;
    const int lr  = lane & 7;

    uint32_t aoff[4];
    #pragma unroll
    for (int mi = 0; mi < 4; mi++)
        aoff[mi] = (uint32_t)((wm * 64 + mi * 16 + qlo * 8 + lr) * 128);
    uint32_t boff[4];
    #pragma unroll
    for (int p = 0; p < 4; p++)
        boff[p] = (uint32_t)(A_BYTES + (wn * 64 + p * 16 + qhi * 8 + lr) * 128);
    const uint32_t lxor = (uint32_t)lr;

    // --- fragment double buffers + accumulators: 4 (m) x 8 (n) tiles of 16x8 ---
    uint32_t af[2][4][4], bf[2][8][2];
    float acc[4][8][4];
    #pragma unroll
    for (int mi = 0; mi < 4; mi++)
        #pragma unroll
        for (int ni = 0; ni < 8; ni++)
            #pragma unroll
            for (int r = 0; r < 4; r++) acc[mi][ni][r] = 0.0f;

    auto load_frags = [&](int buf, uint32_t sbase, int kt) {
        const uint32_t ca = (uint32_t)(2 * kt) + (uint32_t)qhi;
        #pragma unroll
        for (int mi = 0; mi < 4; mi++)
            ldsm4(af[buf][mi], sbase + aoff[mi] + ((ca ^ lxor) << 4));
        const uint32_t cb = (uint32_t)(2 * kt) + (uint32_t)qlo;
        #pragma unroll
        for (int p = 0; p < 4; p++) {
            uint32_t r[4];
            ldsm4(r, sbase + boff[p] + ((cb ^ lxor) << 4));
            bf[buf][2 * p][0]     = r[0];
            bf[buf][2 * p][1]     = r[1];
            bf[buf][2 * p + 1][0] = r[2];
            bf[buf][2 * p + 1][1] = r[3];
        }
    };

    // --- prologue: wait stage 0, preload its kt=0 fragments ---
    mbar_wait(sb + SMEM_FULL(0), 0u);
    load_frags(0, sb + SMEM_DATA, 0);

    // --- main loop: kt-level fragment pipelining, mbarrier-ordered stages ---
    for (int tt = 0; tt < NITER; tt++) {
        const int slot = tt % STAGES;
        const uint32_t scur = sb + SMEM_DATA + (uint32_t)slot * STAGE_BYTES;
        const uint32_t snxt = sb + SMEM_DATA + (uint32_t)((tt + 1) % STAGES) * STAGE_BYTES;

        #pragma unroll
        for (int kt = 0; kt < 4; kt++) {
            const int cur = kt & 1;
            const int nxt = cur ^ 1;
            if (kt < 3) {
                load_frags(nxt, scur, kt + 1);
            } else {
                if (lane == 0) mbar_arrive(sb + SMEM_EMPTY(slot));   // done reading scur
                if (tt + 1 < NITER) {
                    mbar_wait(sb + SMEM_FULL((tt + 1) % STAGES),
                              (uint32_t)(((tt + 1) / STAGES) & 1));
                    load_frags(nxt, snxt, 0);
                }
            }
            #pragma unroll
            for (int ni = 0; ni < 8; ni++)
                #pragma unroll
                for (int mi = 0; mi < 4; mi++)
                    mma_f16(acc[mi][ni], af[cur][mi], bf[cur][ni]);
        }

        if (tid == 0 && tt + STAGES < NITER) produce(tt + STAGES);
    }
    __syncthreads();

    // --- epilogue: accums -> smem gates buffer [128][GPITCH] ---
    const int g  = lane >> 2;
    const int t4 = lane & 3;
    float* gs = (float*)(smem + SMEM_DATA);
    #pragma unroll
    for (int mi = 0; mi < 4; mi++) {
        #pragma unroll
        for (int ni = 0; ni < 8; ni++) {
            int row = wm * 64 + mi * 16 + g;
            int col = wn * 64 + ni * 8 + 2 * t4;
            *(float2*)(gs + row * GPITCH + col)       = make_float2(acc[mi][ni][0], acc[mi][ni][1]);
            *(float2*)(gs + (row + 8) * GPITCH + col) = make_float2(acc[mi][ni][2], acc[mi][ni][3]);
        }
    }
    __syncthreads();

    // --- pointwise LSTM + writes (float4 over 32 h cols) ---
    const float* bs = (const float*)(smem + SMEM_BIAS);
    #pragma unroll
    for (int rep = 0; rep < 8; rep++) {
        int idx = tid + THREADS * rep;    // 0..1023
        int m  = idx >> 3;                // 0..127
        int h4 = idx & 7;                 // float4 over 32 h cols
        const float* grow = gs + m * GPITCH;

        float4 zi = *(const float4*)(grow + 0 * 32 + h4 * 4);
        float4 zf = *(const float4*)(grow + 1 * 32 + h4 * 4);
        float4 zg = *(const float4*)(grow + 2 * 32 + h4 * 4);
        float4 zo = *(const float4*)(grow + 3 * 32 + h4 * 4);
        float4 vbi = *(const float4*)(bs + 0 * 32 + h4 * 4);
        float4 vbf = *(const float4*)(bs + 1 * 32 + h4 * 4);
        float4 vbg = *(const float4*)(bs + 2 * 32 + h4 * 4);
        float4 vbo = *(const float4*)(bs + 3 * 32 + h4 * 4);

        size_t go = (size_t)(m0 + m) * H_DIM + h0 + h4 * 4;
        float4 cp = *(const float4*)(cprev + go);

        float hv[4], cv[4];
        float azi[4] = {zi.x, zi.y, zi.z, zi.w};
        float azf[4] = {zf.x, zf.y, zf.z, zf.w};
        float azg[4] = {zg.x, zg.y, zg.z, zg.w};
        float azo[4] = {zo.x, zo.y, zo.z, zo.w};
        float abi[4] = {vbi.x, vbi.y, vbi.z, vbi.w};
        float abf[4] = {vbf.x, vbf.y, vbf.z, vbf.w};
        float abg[4] = {vbg.x, vbg.y, vbg.z, vbg.w};
        float abo[4] = {vbo.x, vbo.y, vbo.z, vbo.w};
        float acp[4] = {cp.x, cp.y, cp.z, cp.w};

        #pragma unroll
        for (int j = 0; j < 4; j++) {
            float ig = sigmoidf_fast(azi[j] + abi[j]);
            float fg = sigmoidf_fast(azf[j] + abf[j]);
            float gg = tanhf_fast(azg[j] + abg[j]);
            float og = sigmoidf_fast(azo[j] + abo[j]);
            cv[j] = fg * acp[j] + ig * gg;
            hv[j] = og * tanhf_fast(cv[j]);
        }
        float4 hv4 = make_float4(hv[0], hv[1], hv[2], hv[3]);
        float4 cv4 = make_float4(cv[0], cv[1], cv[2], cv[3]);
        *(float4*)(out_h + go) = hv4;
        if (out_h2) *(float4*)(out_h2 + go) = hv4;
        if (out_c)  *(float4*)(out_c + go)  = cv4;
    }
}

extern "C" void kernel_launch(void* const* d_in, const int* in_sizes, int n_in,
                              void* d_out, int out_size) {
    const float* x      = (const float*)d_in[0];
    const float* h_prev = (const float*)d_in[1];
    const float* c_prev = (const float*)d_in[2];
    const float* W_ii = (const float*)d_in[3];
    const float* W_hi = (const float*)d_in[4];
    const float* b_i  = (const float*)d_in[5];
    const float* W_if = (const float*)d_in[6];
    const float* W_hf = (const float*)d_in[7];
    const float* b_f  = (const float*)d_in[8];
    const float* W_ig = (const float*)d_in[9];
    const float* W_hg = (const float*)d_in[10];
    const float* b_g  = (const float*)d_in[11];
    const float* W_io = (const float*)d_in[12];
    const float* W_ho = (const float*)d_in[13];
    const float* b_o  = (const float*)d_in[14];

    float* out = (float*)d_out;
    const int HB = B_DIM * H_DIM;   // 4194304
    float* oh  = out;
    float* oh2 = nullptr;
    float* oc  = nullptr;
    if (out_size >= 3 * HB)      { oh2 = out + HB; oc = out + 2 * HB; }
    else if (out_size >= 2 * HB) { oc = out + HB; }

    static bool attr_set = false;
    if (!attr_set) {
        cudaFuncSetAttribute(lstm_kernel, cudaFuncAttributeMaxDynamicSharedMemorySize, SMEM_TOTAL);
        attr_set = true;
    }

    // fp16 conversion pre-pass (merged; writes pre-swizzled tiled layout)
    {
        int n8 = (B_DIM * K_DIM) / 8;     // 1,048,576 chunks per half
        conv_kernel<<<2 * (n8 / 256), 256>>>(x, h_prev,
                                             W_ii, W_hi, W_if, W_hf,
                                             W_ig, W_hg, W_io, W_ho);
    }

    lstm_kernel<<<(B_DIM / BM) * (H_DIM / BH), THREADS, SMEM_TOTAL>>>(
        c_prev, b_i, b_f, b_g, b_o, oh, oh2, oc);
}

// round 13
// speedup vs baseline: 1.4254x; 1.0533x over previous
#include <cuda_runtime.h>
#include <cuda_fp16.h>
#include <cstdint>
#include <cstddef>

// Problem shape
#define B_DIM 4096
#define IN_DIM 1024
#define H_DIM 1024
#define K_DIM 2048          // IN + H concatenated along K
// Tiling
#define BM 128              // batch rows per CTA
#define BH 32               // h columns per CTA
#define BN 128              // 4 gates * BH
#define BK 64               // K per stage (64 fp16 = 128B row)
#define STAGES 3
#define NITER (K_DIM / BK)  // 32
#define THREADS 128         // 4 warps, 2x2, warp tile 64x64

// fp16 scratch in PRE-SWIZZLED tiled layout (static device arrays; no allocation)
//   g_xh: [mtile 0..31][stage 0..31] 16KB blocks; 128 rows x 128B, XOR swizzle
//   g_w : [htile 0..31][stage 0..31] 16KB blocks; 128 rows (4 gates x 32) x 128B, XOR swizzle
__device__ __half g_xh[(size_t)B_DIM * K_DIM];
__device__ __half g_w[(size_t)4 * H_DIM * K_DIM];

// Shared memory layout
#define A_BYTES (BM * 128)                         // 16384
#define B_BYTES (BN * 128)                         // 16384
#define STAGE_BYTES (A_BYTES + B_BYTES)            // 32768
#define SMEM_FULL(s)  (16 + 8 * (s))               // full barriers
#define SMEM_EMPTY(s) (48 + 8 * (s))               // empty barriers
#define SMEM_BIAS 128                              // 4*32 floats = 512B
#define SMEM_DATA 2048
#define SMEM_TOTAL (SMEM_DATA + STAGES * STAGE_BYTES)  // 100352  (x2 CTAs <= 227KB)
// Epilogue gates buffer overlays stage area: 128 x 136 x 4 = 69632 <= 98304
#define GPITCH 136

__device__ __forceinline__ uint32_t smem_u32(const void* p) {
    uint32_t a;
    asm("{ .reg .u64 t; cvta.to.shared.u64 t, %1; cvt.u32.u64 %0, t; }" : "=r"(a) : "l"(p));
    return a;
}

__device__ __forceinline__ void mbar_init(uint32_t addr, uint32_t cnt) {
    asm volatile("mbarrier.init.shared.b64 [%0], %1;" :: "r"(addr), "r"(cnt) : "memory");
}
__device__ __forceinline__ void mbar_expect_tx(uint32_t addr, uint32_t tx) {
    asm volatile("mbarrier.arrive.expect_tx.shared.b64 _, [%0], %1;" :: "r"(addr), "r"(tx) : "memory");
}
__device__ __forceinline__ void mbar_arrive(uint32_t addr) {
    asm volatile("mbarrier.arrive.shared.b64 _, [%0];" :: "r"(addr) : "memory");
}
__device__ __forceinline__ void mbar_wait(uint32_t addr, uint32_t parity) {
    uint32_t done;
    asm volatile(
        "{\n\t.reg .pred p;\n\t"
        "mbarrier.try_wait.parity.acquire.cta.shared::cta.b64 p, [%1], %2;\n\t"
        "selp.b32 %0, 1, 0, p;\n\t}"
        : "=r"(done) : "r"(addr), "r"(parity) : "memory");
    while (!done) {
        asm volatile(
            "{\n\t.reg .pred p;\n\t"
            "mbarrier.try_wait.parity.acquire.cta.shared::cta.b64 p, [%1], %2, 0x989680;\n\t"
            "selp.b32 %0, 1, 0, p;\n\t}"
            : "=r"(done) : "r"(addr), "r"(parity) : "memory");
    }
}
__device__ __forceinline__ void bulk_g2s(uint32_t dst, const void* src, uint32_t bytes, uint32_t mbar) {
    asm volatile(
        "cp.async.bulk.shared::cluster.global.mbarrier::complete_tx::bytes [%0], [%1], %2, [%3];"
        :: "r"(dst), "l"(src), "r"(bytes), "r"(mbar) : "memory");
}

__device__ __forceinline__ void ldsm4(uint32_t* r, uint32_t addr) {
    asm volatile("ldmatrix.sync.aligned.m8n8.x4.shared.b16 {%0,%1,%2,%3}, [%4];"
                 : "=r"(r[0]), "=r"(r[1]), "=r"(r[2]), "=r"(r[3]) : "r"(addr));
}

__device__ __forceinline__ void mma_f16(float* d, const uint32_t* a, const uint32_t* b) {
    asm volatile(
        "mma.sync.aligned.m16n8k16.row.col.f32.f16.f16.f32 "
        "{%0, %1, %2, %3}, {%4, %5, %6, %7}, {%8, %9}, {%0, %1, %2, %3};"
        : "+f"(d[0]), "+f"(d[1]), "+f"(d[2]), "+f"(d[3])
        : "r"(a[0]), "r"(a[1]), "r"(a[2]), "r"(a[3]), "r"(b[0]), "r"(b[1]));
}

__device__ __forceinline__ float sigmoidf_fast(float x) {
    return 1.0f / (1.0f + __expf(-x));
}
__device__ __forceinline__ float tanhf_fast(float x) {
    float e = __expf(2.0f * x);
    return (e - 1.0f) / (e + 1.0f);
}

// ---------------- merged conversion kernel (writes pre-swizzled tiled layout) ----------------
__global__ void __launch_bounds__(256)
conv_kernel(const float* __restrict__ x, const float* __restrict__ h,
            const float* __restrict__ Wxi, const float* __restrict__ Whi,
            const float* __restrict__ Wxf, const float* __restrict__ Whf,
            const float* __restrict__ Wxg, const float* __restrict__ Whg,
            const float* __restrict__ Wxo, const float* __restrict__ Who) {
    const int half = gridDim.x >> 1;
    size_t i = (size_t)(blockIdx.x % half) * blockDim.x + threadIdx.x;  // 0 .. 1M-1
    int rg     = (int)(i >> 8);          // source row (0..4095)
    int kchunk = (int)(i & 255);         // 16B chunk along K
    int stage  = kchunk >> 3;            // 0..31
    int c      = kchunk & 7;             // chunk within 128B row
    int col    = stage * 64 + c * 8;     // K element index (8 halves)
    const float* src;
    char* dst;
    if (blockIdx.x < half) {
        src = (col < IN_DIM) ? (x + (size_t)rg * IN_DIM + col)
                             : (h + (size_t)rg * H_DIM + (col - IN_DIM));
        int r  = rg & 127;
        int mt = rg >> 7;
        dst = (char*)g_xh + ((size_t)(mt * 32 + stage)) * A_BYTES
            + r * 128 + ((c ^ (r & 7)) << 4);
    } else {
        const float* const Wx[4] = {Wxi, Wxf, Wxg, Wxo};
        const float* const Wh[4] = {Whi, Whf, Whg, Who};
        int gate = rg >> 10;
        int hh   = rg & 1023;
        int ht   = hh >> 5;              // 0..31 h tiles of 32
        int r    = gate * 32 + (hh & 31);// row within 128-row B tile (gate-major)
        src = (col < IN_DIM) ? (Wx[gate] + (size_t)hh * IN_DIM + col)
                             : (Wh[gate] + (size_t)hh * H_DIM + (col - IN_DIM));
        dst = (char*)g_w + ((size_t)(ht * 32 + stage)) * B_BYTES
            + r * 128 + ((c ^ (r & 7)) << 4);
    }
    float4 v0 = *(const float4*)(src);
    float4 v1 = *(const float4*)(src + 4);
    __half2 h0 = __floats2half2_rn(v0.x, v0.y);
    __half2 h1 = __floats2half2_rn(v0.z, v0.w);
    __half2 h2 = __floats2half2_rn(v1.x, v1.y);
    __half2 h3 = __floats2half2_rn(v1.z, v1.w);
    uint4 o;
    o.x = *(uint32_t*)&h0; o.y = *(uint32_t*)&h1;
    o.z = *(uint32_t*)&h2; o.w = *(uint32_t*)&h3;
    *(uint4*)dst = o;
}

// ---------------- main fused GEMM + LSTM kernel ----------------
// 4 warps (one per SMSP), 2 CTAs/SM, 64x64 warp tiles, kt-level fragment
// double-buffering. R12: early empty-arrive (kt=2) + round-robin producer
// so no single warp absorbs the inter-warp skew every iteration.

__global__ void __launch_bounds__(THREADS, 2)
lstm_kernel(const float* __restrict__ cprev,
            const float* __restrict__ bi, const float* __restrict__ bfv,
            const float* __restrict__ bg, const float* __restrict__ bo,
            float* __restrict__ out_h, float* out_h2, float* out_c)
{
    extern __shared__ char smem[];
    const uint32_t sb = smem_u32(smem);
    const int tid  = threadIdx.x;
    const int lane = tid & 31;
    const int warp = tid >> 5;
    const int wm   = warp >> 1;   // 0..1  (64-row tiles)
    const int wn   = warp & 1;    // 0..1  (64-col tiles)

    const int bid   = blockIdx.x;
    const int htile = bid & 31;   // 32 h tiles
    const int mtile = bid >> 5;   // 32 m tiles
    const int m0 = mtile * BM;
    const int h0 = htile * BH;

    // --- barrier init + bias staging ---
    if (tid == 0) {
        #pragma unroll
        for (int s = 0; s < STAGES; s++) {
            mbar_init(sb + SMEM_FULL(s), 1);     // producer expect_tx
            mbar_init(sb + SMEM_EMPTY(s), 4);    // one arrive per warp
        }
    }
    if (tid < 32) {
        float* bs = (float*)(smem + SMEM_BIAS);
        bs[0 * 32 + tid] = bi[h0 + tid];
        bs[1 * 32 + tid] = bfv[h0 + tid];
        bs[2 * 32 + tid] = bg[h0 + tid];
        bs[3 * 32 + tid] = bo[h0 + tid];
    }
    __syncthreads();

    // --- producer: 2 bulk copies per stage (round-robin issuing warp) ---
    const char* asrc = (const char*)g_xh + (size_t)mtile * 32 * A_BYTES;
    const char* bsrc = (const char*)g_w  + (size_t)htile * 32 * B_BYTES;
    auto produce = [&](int f) {
        int slot = f % STAGES;
        if (f >= STAGES) mbar_wait(sb + SMEM_EMPTY(slot), (uint32_t)((f / STAGES - 1) & 1));
        uint32_t dst = sb + SMEM_DATA + (uint32_t)slot * STAGE_BYTES;
        uint32_t mb  = sb + SMEM_FULL(slot);
        mbar_expect_tx(mb, STAGE_BYTES);
        bulk_g2s(dst, asrc + (size_t)f * A_BYTES, A_BYTES, mb);
        bulk_g2s(dst + A_BYTES, bsrc + (size_t)f * B_BYTES, B_BYTES, mb);
    };
    if (tid == 0) { produce(0); produce(1); produce(2); }

    // --- ldmatrix per-lane geometry ---
    const int q   = lane >> 3;      // 0..3
    const int qlo = q & 1;
    const int qhi = q >> 1;
    const int lr  = lane & 7;

    uint32_t aoff[4];
    #pragma unroll
    for (int mi = 0; mi < 4; mi++)
        aoff[mi] = (uint32_t)((wm * 64 + mi * 16 + qlo * 8 + lr) * 128);
    uint32_t boff[4];
    #pragma unroll
    for (int p = 0; p < 4; p++)
        boff[p] = (uint32_t)(A_BYTES + (wn * 64 + p * 16 + qhi * 8 + lr) * 128);
    const uint32_t lxor = (uint32_t)lr;

    // --- fragment double buffers + accumulators: 4 (m) x 8 (n) tiles of 16x8 ---
    uint32_t af[2][4][4], bf[2][8][2];
    float acc[4][8][4];
    #pragma unroll
    for (int mi = 0; mi < 4; mi++)
        #pragma unroll
        for (int ni = 0; ni < 8; ni++)
            #pragma unroll
            for (int r = 0; r < 4; r++) acc[mi][ni][r] = 0.0f;

    auto load_frags = [&](int buf, uint32_t sbase, int kt) {
        const uint32_t ca = (uint32_t)(2 * kt) + (uint32_t)qhi;
        #pragma unroll
        for (int mi = 0; mi < 4; mi++)
            ldsm4(af[buf][mi], sbase + aoff[mi] + ((ca ^ lxor) << 4));
        const uint32_t cb = (uint32_t)(2 * kt) + (uint32_t)qlo;
        #pragma unroll
        for (int p = 0; p < 4; p++) {
            uint32_t r[4];
            ldsm4(r, sbase + boff[p] + ((cb ^ lxor) << 4));
            bf[buf][2 * p][0]     = r[0];
            bf[buf][2 * p][1]     = r[1];
            bf[buf][2 * p + 1][0] = r[2];
            bf[buf][2 * p + 1][1] = r[3];
        }
    };

    // --- prologue: wait stage 0, preload its kt=0 fragments ---
    mbar_wait(sb + SMEM_FULL(0), 0u);
    load_frags(0, sb + SMEM_DATA, 0);

    // --- main loop: kt-level fragment pipelining, mbarrier-ordered stages ---
    for (int tt = 0; tt < NITER; tt++) {
        const int slot = tt % STAGES;
        const uint32_t scur = sb + SMEM_DATA + (uint32_t)slot * STAGE_BYTES;
        const uint32_t snxt = sb + SMEM_DATA + (uint32_t)((tt + 1) % STAGES) * STAGE_BYTES;

        #pragma unroll
        for (int kt = 0; kt < 4; kt++) {
            const int cur = kt & 1;
            const int nxt = cur ^ 1;
            if (kt < 3) {
                load_frags(nxt, scur, kt + 1);
                // kt==2 issues the final reads of scur -> this warp is done with
                // the slot; arrive early so the producer can start refilling it
                // while we run kt2+kt3 MMAs. (Bulk-copy first-write latency
                // >> in-flight ldsm completion, so no read/write hazard.)
                if (kt == 2 && lane == 0) mbar_arrive(sb + SMEM_EMPTY(slot));
            } else {
                if (tt + 1 < NITER) {
                    mbar_wait(sb + SMEM_FULL((tt + 1) % STAGES),
                              (uint32_t)(((tt + 1) / STAGES) & 1));
                    load_frags(nxt, snxt, 0);
                }
            }
            #pragma unroll
            for (int ni = 0; ni < 8; ni++)
                #pragma unroll
                for (int mi = 0; mi < 4; mi++)
                    mma_f16(acc[mi][ni], af[cur][mi], bf[cur][ni]);
        }

        // Round-robin producer: a different warp issues each stage's copies,
        // so the empty-wait skew is not always absorbed by warp 0.
        if (lane == 0 && warp == (tt & 3) && tt + STAGES < NITER) produce(tt + STAGES);
    }
    __syncthreads();

    // --- epilogue: accums -> smem gates buffer [128][GPITCH] ---
    const int g  = lane >> 2;
    const int t4 = lane & 3;
    float* gs = (float*)(smem + SMEM_DATA);
    #pragma unroll
    for (int mi = 0; mi < 4; mi++) {
        #pragma unroll
        for (int ni = 0; ni < 8; ni++) {
            int row = wm * 64 + mi * 16 + g;
            int col = wn * 64 + ni * 8 + 2 * t4;
            *(float2*)(gs + row * GPITCH + col)       = make_float2(acc[mi][ni][0], acc[mi][ni][1]);
            *(float2*)(gs + (row + 8) * GPITCH + col) = make_float2(acc[mi][ni][2], acc[mi][ni][3]);
        }
    }
    __syncthreads();

    // --- pointwise LSTM + writes (float4 over 32 h cols) ---
    const float* bs = (const float*)(smem + SMEM_BIAS);
    #pragma unroll
    for (int rep = 0; rep < 8; rep++) {
        int idx = tid + THREADS * rep;    // 0..1023
        int m  = idx >> 3;                // 0..127
        int h4 = idx & 7;                 // float4 over 32 h cols
        const float* grow = gs + m * GPITCH;

        float4 zi = *(const float4*)(grow + 0 * 32 + h4 * 4);
        float4 zf = *(const float4*)(grow + 1 * 32 + h4 * 4);
        float4 zg = *(const float4*)(grow + 2 * 32 + h4 * 4);
        float4 zo = *(const float4*)(grow + 3 * 32 + h4 * 4);
        float4 vbi = *(const float4*)(bs + 0 * 32 + h4 * 4);
        float4 vbf = *(const float4*)(bs + 1 * 32 + h4 * 4);
        float4 vbg = *(const float4*)(bs + 2 * 32 + h4 * 4);
        float4 vbo = *(const float4*)(bs + 3 * 32 + h4 * 4);

        size_t go = (size_t)(m0 + m) * H_DIM + h0 + h4 * 4;
        float4 cp = *(const float4*)(cprev + go);

        float hv[4], cv[4];
        float azi[4] = {zi.x, zi.y, zi.z, zi.w};
        float azf[4] = {zf.x, zf.y, zf.z, zf.w};
        float azg[4] = {zg.x, zg.y, zg.z, zg.w};
        float azo[4] = {zo.x, zo.y, zo.z, zo.w};
        float abi[4] = {vbi.x, vbi.y, vbi.z, vbi.w};
        float abf[4] = {vbf.x, vbf.y, vbf.z, vbf.w};
        float abg[4] = {vbg.x, vbg.y, vbg.z, vbg.w};
        float abo[4] = {vbo.x, vbo.y, vbo.z, vbo.w};
        float acp[4] = {cp.x, cp.y, cp.z, cp.w};

        #pragma unroll
        for (int j = 0; j < 4; j++) {
            float ig = sigmoidf_fast(azi[j] + abi[j]);
            float fg = sigmoidf_fast(azf[j] + abf[j]);
            float gg = tanhf_fast(azg[j] + abg[j]);
            float og = sigmoidf_fast(azo[j] + abo[j]);
            cv[j] = fg * acp[j] + ig * gg;
            hv[j] = og * tanhf_fast(cv[j]);
        }
        float4 hv4 = make_float4(hv[0], hv[1], hv[2], hv[3]);
        float4 cv4 = make_float4(cv[0], cv[1], cv[2], cv[3]);
        *(float4*)(out_h + go) = hv4;
        if (out_h2) *(float4*)(out_h2 + go) = hv4;
        if (out_c)  *(float4*)(out_c + go)  = cv4;
    }
}

extern "C" void kernel_launch(void* const* d_in, const int* in_sizes, int n_in,
                              void* d_out, int out_size) {
    const float* x      = (const float*)d_in[0];
    const float* h_prev = (const float*)d_in[1];
    const float* c_prev = (const float*)d_in[2];
    const float* W_ii = (const float*)d_in[3];
    const float* W_hi = (const float*)d_in[4];
    const float* b_i  = (const float*)d_in[5];
    const float* W_if = (const float*)d_in[6];
    const float* W_hf = (const float*)d_in[7];
    const float* b_f  = (const float*)d_in[8];
    const float* W_ig = (const float*)d_in[9];
    const float* W_hg = (const float*)d_in[10];
    const float* b_g  = (const float*)d_in[11];
    const float* W_io = (const float*)d_in[12];
    const float* W_ho = (const float*)d_in[13];
    const float* b_o  = (const float*)d_in[14];

    float* out = (float*)d_out;
    const int HB = B_DIM * H_DIM;   // 4194304
    float* oh  = out;
    float* oh2 = nullptr;
    float* oc  = nullptr;
    if (out_size >= 3 * HB)      { oh2 = out + HB; oc = out + 2 * HB; }
    else if (out_size >= 2 * HB) { oc = out + HB; }

    static bool attr_set = false;
    if (!attr_set) {
        cudaFuncSetAttribute(lstm_kernel, cudaFuncAttributeMaxDynamicSharedMemorySize, SMEM_TOTAL);
        attr_set = true;
    }

    // fp16 conversion pre-pass (merged; writes pre-swizzled tiled layout)
    {
        int n8 = (B_DIM * K_DIM) / 8;     // 1,048,576 chunks per half
        conv_kernel<<<2 * (n8 / 256), 256>>>(x, h_prev,
                                             W_ii, W_hi, W_if, W_hf,
                                             W_ig, W_hg, W_io, W_ho);
    }

    lstm_kernel<<<(B_DIM / BM) * (H_DIM / BH), THREADS, SMEM_TOTAL>>>(
        c_prev, b_i, b_f, b_g, b_o, oh, oh2, oc);
}

// round 14
// speedup vs baseline: 1.4965x; 1.0499x over previous
#include <cuda_runtime.h>
#include <cuda_fp16.h>
#include <cstdint>
#include <cstddef>

// Problem shape
#define B_DIM 4096
#define IN_DIM 1024
#define H_DIM 1024
#define K_DIM 2048          // IN + H (concatenated K)
// Tiling
#define BM 128              // batch rows per CTA
#define BH 32               // h columns per CTA
#define BN 128              // 4 gates * BH
#define BK 64               // K per stage (64 fp16 = 128B row)
#define STAGES 3
#define NITER (K_DIM / BK)  // 32
#define THREADS 128         // 4 warps, 2x2, warp tile 64x64

// fp16 scratch in PRE-SWIZZLED tiled layout (static device arrays; no allocation)
__device__ __half g_xh[(size_t)B_DIM * K_DIM];
__device__ __half g_w[(size_t)4 * H_DIM * K_DIM];

// Shared memory layout
#define A_BYTES (BM * 128)                         // 16384
#define B_BYTES (BN * 128)                         // 16384
#define STAGE_BYTES (A_BYTES + B_BYTES)            // 32768
#define SMEM_FULL(s)  (16 + 8 * (s))
#define SMEM_EMPTY(s) (48 + 8 * (s))
#define SMEM_BIAS 128
#define SMEM_DATA 2048
#define SMEM_TOTAL (SMEM_DATA + STAGES * STAGE_BYTES)  // 100352 (x2 CTAs <= 227KB)
#define GPITCH 136

__device__ __forceinline__ uint32_t smem_u32(const void* p) {
    uint32_t a;
    asm("{ .reg .u64 t; cvta.to.shared.u64 t, %1; cvt.u32.u64 %0, t; }" : "=r"(a) : "l"(p));
    return a;
}

__device__ __forceinline__ void mbar_init(uint32_t addr, uint32_t cnt) {
    asm volatile("mbarrier.init.shared.b64 [%0], %1;" :: "r"(addr), "r"(cnt) : "memory");
}
__device__ __forceinline__ void mbar_expect_tx(uint32_t addr, uint32_t tx) {
    asm volatile("mbarrier.arrive.expect_tx.shared.b64 _, [%0], %1;" :: "r"(addr), "r"(tx) : "memory");
}
__device__ __forceinline__ void mbar_arrive(uint32_t addr) {
    asm volatile("mbarrier.arrive.shared.b64 _, [%0];" :: "r"(addr) : "memory");
}
__device__ __forceinline__ void mbar_wait(uint32_t addr, uint32_t parity) {
    uint32_t done;
    asm volatile(
        "{\n\t.reg .pred p;\n\t"
        "mbarrier.try_wait.parity.acquire.cta.shared::cta.b64 p, [%1], %2;\n\t"
        "selp.b32 %0, 1, 0, p;\n\t}"
        : "=r"(done) : "r"(addr), "r"(parity) : "memory");
    while (!done) {
        asm volatile(
            "{\n\t.reg .pred p;\n\t"
            "mbarrier.try_wait.parity.acquire.cta.shared::cta.b64 p, [%1], %2, 0x989680;\n\t"
            "selp.b32 %0, 1, 0, p;\n\t}"
            : "=r"(done) : "r"(addr), "r"(parity) : "memory");
    }
}
__device__ __forceinline__ void bulk_g2s(uint32_t dst, const void* src, uint32_t bytes, uint32_t mbar) {
    asm volatile(
        "cp.async.bulk.shared::cluster.global.mbarrier::complete_tx::bytes [%0], [%1], %2, [%3];"
        :: "r"(dst), "l"(src), "r"(bytes), "r"(mbar) : "memory");
}

__device__ __forceinline__ void ldsm4(uint32_t* r, uint32_t addr) {
    asm volatile("ldmatrix.sync.aligned.m8n8.x4.shared.b16 {%0,%1,%2,%3}, [%4];"
                 : "=r"(r[0]), "=r"(r[1]), "=r"(r[2]), "=r"(r[3]) : "r"(addr));
}

__device__ __forceinline__ void mma_f16(float* d, const uint32_t* a, const uint32_t* b) {
    asm volatile(
        "mma.sync.aligned.m16n8k16.row.col.f32.f16.f16.f32 "
        "{%0, %1, %2, %3}, {%4, %5, %6, %7}, {%8, %9}, {%0, %1, %2, %3};"
        : "+f"(d[0]), "+f"(d[1]), "+f"(d[2]), "+f"(d[3])
        : "r"(a[0]), "r"(a[1]), "r"(a[2]), "r"(a[3]), "r"(b[0]), "r"(b[1]));
}

__device__ __forceinline__ float sigmoidf_fast(float x) {
    return 1.0f / (1.0f + __expf(-x));
}
__device__ __forceinline__ float tanhf_fast(float x) {
    float e = __expf(2.0f * x);
    return (e - 1.0f) / (e + 1.0f);
}

// ---------------- merged conversion kernel (writes pre-swizzled tiled layout) ----------------
__global__ void __launch_bounds__(256)
conv_kernel(const float* __restrict__ x, const float* __restrict__ h,
            const float* __restrict__ Wxi, const float* __restrict__ Whi,
            const float* __restrict__ Wxf, const float* __restrict__ Whf,
            const float* __restrict__ Wxg, const float* __restrict__ Whg,
            const float* __restrict__ Wxo, const float* __restrict__ Who) {
    const int half = gridDim.x >> 1;
    size_t i = (size_t)(blockIdx.x % half) * blockDim.x + threadIdx.x;  // 0 .. 1M-1
    int rg     = (int)(i >> 8);
    int kchunk = (int)(i & 255);
    int stage  = kchunk >> 3;
    int c      = kchunk & 7;
    int col    = stage * 64 + c * 8;
    const float* src;
    char* dst;
    if (blockIdx.x < half) {
        src = (col < IN_DIM) ? (x + (size_t)rg * IN_DIM + col)
                             : (h + (size_t)rg * H_DIM + (col - IN_DIM));
        int r  = rg & 127;
        int mt = rg >> 7;
        dst = (char*)g_xh + ((size_t)(mt * 32 + stage)) * A_BYTES
            + r * 128 + ((c ^ (r & 7)) << 4);
    } else {
        const float* const Wx[4] = {Wxi, Wxf, Wxg, Wxo};
        const float* const Wh[4] = {Whi, Whf, Whg, Who};
        int gate = rg >> 10;
        int hh   = rg & 1023;
        int ht   = hh >> 5;
        int r    = gate * 32 + (hh & 31);
        src = (col < IN_DIM) ? (Wx[gate] + (size_t)hh * IN_DIM + col)
                             : (Wh[gate] + (size_t)hh * H_DIM + (col - IN_DIM));
        dst = (char*)g_w + ((size_t)(ht * 32 + stage)) * B_BYTES
            + r * 128 + ((c ^ (r & 7)) << 4);
    }
    float4 v0 = *(const float4*)(src);
    float4 v1 = *(const float4*)(src + 4);
    __half2 h0 = __floats2half2_rn(v0.x, v0.y);
    __half2 h1 = __floats2half2_rn(v0.z, v0.w);
    __half2 h2 = __floats2half2_rn(v1.x, v1.y);
    __half2 h3 = __floats2half2_rn(v1.z, v1.w);
    uint4 o;
    o.x = *(uint32_t*)&h0; o.y = *(uint32_t*)&h1;
    o.z = *(uint32_t*)&h2; o.w = *(uint32_t*)&h3;
    *(uint4*)dst = o;
}

// ---------------- main fused GEMM + LSTM kernel ----------------
// R14: kt3 MMAs issued BEFORE the full-wait (hide TRYWAIT ~90cyc behind tensor
// work), stage loop manually unrolled x3 for compile-time slot indices.

__global__ void __launch_bounds__(THREADS, 2)
lstm_kernel(const float* __restrict__ cprev,
            const float* __restrict__ bi, const float* __restrict__ bfv,
            const float* __restrict__ bg, const float* __restrict__ bo,
            float* __restrict__ out_h, float* out_h2, float* out_c)
{
    extern __shared__ char smem[];
    const uint32_t sb = smem_u32(smem);
    const int tid  = threadIdx.x;
    const int lane = tid & 31;
    const int warp = tid >> 5;
    const int wm   = warp >> 1;   // 0..1  (64-row tiles)
    const int wn   = warp & 1;    // 0..1  (64-col tiles)

    const int bid   = blockIdx.x;
    const int htile = bid & 31;   // 32 h tiles
    const int mtile = bid >> 5;   // 32 m tiles
    const int m0 = mtile * BM;
    const int h0 = htile * BH;

    // --- barrier init + bias staging ---
    if (tid == 0) {
        #pragma unroll
        for (int s = 0; s < STAGES; s++) {
            mbar_init(sb + SMEM_FULL(s), 1);     // producer expect_tx
            mbar_init(sb + SMEM_EMPTY(s), 4);    // one arrive per warp
        }
    }
    if (tid < 32) {
        float* bs = (float*)(smem + SMEM_BIAS);
        bs[0 * 32 + tid] = bi[h0 + tid];
        bs[1 * 32 + tid] = bfv[h0 + tid];
        bs[2 * 32 + tid] = bg[h0 + tid];
        bs[3 * 32 + tid] = bo[h0 + tid];
    }
    __syncthreads();

    // --- producer: 2 bulk copies per stage (round-robin issuing warp) ---
    const char* asrc = (const char*)g_xh + (size_t)mtile * 32 * A_BYTES;
    const char* bsrc = (const char*)g_w  + (size_t)htile * 32 * B_BYTES;
    auto produce = [&](int f) {
        int slot = f % STAGES;
        if (f >= STAGES) mbar_wait(sb + SMEM_EMPTY(slot), (uint32_t)((f / STAGES - 1) & 1));
        uint32_t dst = sb + SMEM_DATA + (uint32_t)slot * STAGE_BYTES;
        uint32_t mb  = sb + SMEM_FULL(slot);
        mbar_expect_tx(mb, STAGE_BYTES);
        bulk_g2s(dst, asrc + (size_t)f * A_BYTES, A_BYTES, mb);
        bulk_g2s(dst + A_BYTES, bsrc + (size_t)f * B_BYTES, B_BYTES, mb);
    };
    if (tid == 0) { produce(0); produce(1); produce(2); }

    // --- ldmatrix per-lane geometry ---
    const int q   = lane >> 3;      // 0..3
    const int qlo = q & 1;
    const int qhi = q >> 1;
    const int lr  = lane & 7;

    uint32_t aoff[4];
    #pragma unroll
    for (int mi = 0; mi < 4; mi++)
        aoff[mi] = (uint32_t)((wm * 64 + mi * 16 + qlo * 8 + lr) * 128);
    uint32_t boff[4];
    #pragma unroll
    for (int p = 0; p < 4; p++)
        boff[p] = (uint32_t)(A_BYTES + (wn * 64 + p * 16 + qhi * 8 + lr) * 128);
    const uint32_t lxor = (uint32_t)lr;

    // --- fragment double buffers + accumulators ---
    uint32_t af[2][4][4], bf[2][8][2];
    float acc[4][8][4];
    #pragma unroll
    for (int mi = 0; mi < 4; mi++)
        #pragma unroll
        for (int ni = 0; ni < 8; ni++)
            #pragma unroll
            for (int r = 0; r < 4; r++) acc[mi][ni][r] = 0.0f;

    auto load_frags = [&](int buf, uint32_t sbase, int kt) {
        const uint32_t ca = (uint32_t)(2 * kt) + (uint32_t)qhi;
        #pragma unroll
        for (int mi = 0; mi < 4; mi++)
            ldsm4(af[buf][mi], sbase + aoff[mi] + ((ca ^ lxor) << 4));
        const uint32_t cb = (uint32_t)(2 * kt) + (uint32_t)qlo;
        #pragma unroll
        for (int p = 0; p < 4; p++) {
            uint32_t r[4];
            ldsm4(r, sbase + boff[p] + ((cb ^ lxor) << 4));
            bf[buf][2 * p][0]     = r[0];
            bf[buf][2 * p][1]     = r[1];
            bf[buf][2 * p + 1][0] = r[2];
            bf[buf][2 * p + 1][1] = r[3];
        }
    };

    auto mma_all = [&](int buf) {
        #pragma unroll
        for (int ni = 0; ni < 8; ni++)
            #pragma unroll
            for (int mi = 0; mi < 4; mi++)
                mma_f16(acc[mi][ni], af[buf][mi], bf[buf][ni]);
    };

    // --- prologue: wait stage 0, preload its kt=0 fragments into buf0 ---
    mbar_wait(sb + SMEM_FULL(0), 0u);
    load_frags(0, sb + SMEM_DATA, 0);

    // Stage body. Entry invariant: buf0 holds kt=0 fragments of stage tt.
    // kt3 MMAs issue BEFORE the next-stage full-wait so the tensor pipe stays
    // busy while try_wait resolves. Exit invariant: buf0 holds next kt0.
    auto body = [&](int tt, int slot, int nslot) {
        const uint32_t scur = sb + SMEM_DATA + (uint32_t)slot * STAGE_BYTES;
        const uint32_t snxt = sb + SMEM_DATA + (uint32_t)nslot * STAGE_BYTES;

        load_frags(1, scur, 1);
        mma_all(0);                               // kt0
        load_frags(0, scur, 2);
        mma_all(1);                               // kt1
        load_frags(1, scur, 3);
        if (lane == 0) mbar_arrive(sb + SMEM_EMPTY(slot));  // done reading scur
        mma_all(0);                               // kt2
        mma_all(1);                               // kt3 (before the wait!)
        if (tt + 1 < NITER) {
            mbar_wait(sb + SMEM_FULL(nslot), (uint32_t)(((tt + 1) / STAGES) & 1));
            load_frags(0, snxt, 0);               // next stage kt0
        }
        if (lane == 0 && warp == (tt & 3) && tt + STAGES < NITER) produce(tt + STAGES);
    };

    // --- main loop: x3 unrolled (compile-time slots), 30 + 2 tail ---
    for (int t3 = 0; t3 < 30; t3 += 3) {
        body(t3,     0, 1);
        body(t3 + 1, 1, 2);
        body(t3 + 2, 2, 0);
    }
    body(30, 0, 1);
    body(31, 1, 2);
    __syncthreads();

    // --- epilogue: accums -> smem gates buffer [128][GPITCH] ---
    const int g  = lane >> 2;
    const int t4 = lane & 3;
    float* gs = (float*)(smem + SMEM_DATA);
    #pragma unroll
    for (int mi = 0; mi < 4; mi++) {
        #pragma unroll
        for (int ni = 0; ni < 8; ni++) {
            int row = wm * 64 + mi * 16 + g;
            int col = wn * 64 + ni * 8 + 2 * t4;
            *(float2*)(gs + row * GPITCH + col)       = make_float2(acc[mi][ni][0], acc[mi][ni][1]);
            *(float2*)(gs + (row + 8) * GPITCH + col) = make_float2(acc[mi][ni][2], acc[mi][ni][3]);
        }
    }
    __syncthreads();

    // --- pointwise LSTM + writes (float4 over 32 h cols) ---
    const float* bs = (const float*)(smem + SMEM_BIAS);
    #pragma unroll
    for (int rep = 0; rep < 8; rep++) {
        int idx = tid + THREADS * rep;    // 0..1023
        int m  = idx >> 3;                // 0..127
        int h4 = idx & 7;                 // float4 over 32 h cols
        const float* grow = gs + m * GPITCH;

        float4 zi = *(const float4*)(grow + 0 * 32 + h4 * 4);
        float4 zf = *(const float4*)(grow + 1 * 32 + h4 * 4);
        float4 zg = *(const float4*)(grow + 2 * 32 + h4 * 4);
        float4 zo = *(const float4*)(grow + 3 * 32 + h4 * 4);
        float4 vbi = *(const float4*)(bs + 0 * 32 + h4 * 4);
        float4 vbf = *(const float4*)(bs + 1 * 32 + h4 * 4);
        float4 vbg = *(const float4*)(bs + 2 * 32 + h4 * 4);
        float4 vbo = *(const float4*)(bs + 3 * 32 + h4 * 4);

        size_t go = (size_t)(m0 + m) * H_DIM + h0 + h4 * 4;
        float4 cp = *(const float4*)(cprev + go);

        float hv[4], cv[4];
        float azi[4] = {zi.x, zi.y, zi.z, zi.w};
        float azf[4] = {zf.x, zf.y, zf.z, zf.w};
        float azg[4] = {zg.x, zg.y, zg.z, zg.w};
        float azo[4] = {zo.x, zo.y, zo.z, zo.w};
        float abi[4] = {vbi.x, vbi.y, vbi.z, vbi.w};
        float abf[4] = {vbf.x, vbf.y, vbf.z, vbf.w};
        float abg[4] = {vbg.x, vbg.y, vbg.z, vbg.w};
        float abo[4] = {vbo.x, vbo.y, vbo.z, vbo.w};
        float acp[4] = {cp.x, cp.y, cp.z, cp.w};

        #pragma unroll
        for (int j = 0; j < 4; j++) {
            float ig = sigmoidf_fast(azi[j] + abi[j]);
            float fg = sigmoidf_fast(azf[j] + abf[j]);
            float gg = tanhf_fast(azg[j] + abg[j]);
            float og = sigmoidf_fast(azo[j] + abo[j]);
            cv[j] = fg * acp[j] + ig * gg;
            hv[j] = og * tanhf_fast(cv[j]);
        }
        float4 hv4 = make_float4(hv[0], hv[1], hv[2], hv[3]);
        float4 cv4 = make_float4(cv[0], cv[1], cv[2], cv[3]);
        *(float4*)(out_h + go) = hv4;
        if (out_h2) *(float4*)(out_h2 + go) = hv4;
        if (out_c)  *(float4*)(out_c + go)  = cv4;
    }
}

extern "C" void kernel_launch(void* const* d_in, const int* in_sizes, int n_in,
                              void* d_out, int out_size) {
    const float* x      = (const float*)d_in[0];
    const float* h_prev = (const float*)d_in[1];
    const float* c_prev = (const float*)d_in[2];
    const float* W_ii = (const float*)d_in[3];
    const float* W_hi = (const float*)d_in[4];
    const float* b_i  = (const float*)d_in[5];
    const float* W_if = (const float*)d_in[6];
    const float* W_hf = (const float*)d_in[7];
    const float* b_f  = (const float*)d_in[8];
    const float* W_ig = (const float*)d_in[9];
    const float* W_hg = (const float*)d_in[10];
    const float* b_g  = (const float*)d_in[11];
    const float* W_io = (const float*)d_in[12];
    const float* W_ho = (const float*)d_in[13];
    const float* b_o  = (const float*)d_in[14];

    float* out = (float*)d_out;
    const int HB = B_DIM * H_DIM;   // 4194304
    float* oh  = out;
    float* oh2 = nullptr;
    float* oc  = nullptr;
    if (out_size >= 3 * HB)      { oh2 = out + HB; oc = out + 2 * HB; }
    else if (out_size >= 2 * HB) { oc = out + HB; }

    static bool attr_set = false;
    if (!attr_set) {
        cudaFuncSetAttribute(lstm_kernel, cudaFuncAttributeMaxDynamicSharedMemorySize, SMEM_TOTAL);
        attr_set = true;
    }

    // fp16 conversion pre-pass (merged; writes pre-swizzled tiled layout)
    {
        int n8 = (B_DIM * K_DIM) / 8;     // 1,048,576 chunks per half
        conv_kernel<<<2 * (n8 / 256), 256>>>(x, h_prev,
                                             W_ii, W_hi, W_if, W_hf,
                                             W_ig, W_hg, W_io, W_ho);
    }

    lstm_kernel<<<(B_DIM / BM) * (H_DIM / BH), THREADS, SMEM_TOTAL>>>(
        c_prev, b_i, b_f, b_g, b_o, oh, oh2, oc);
}